// round 9
// baseline (speedup 1.0000x reference)
#include <cuda_runtime.h>

// ---------------------------------------------------------------------------
// GAT returning only h[N-1]: cone pruning, single persistent kernel.
// R9 = R6 base (best: 40.6us) with: 3 grid barriers instead of 4 (P4+P5 run
// entirely on block 0 after barrier 3; blocks 1..147 clean flags and exit,
// overlapped), warp-shfl softmax, __expf, smem union (bitmap / P4 lists).
// ---------------------------------------------------------------------------

#define NB       148
#define NT       512
#define SCAN_U   4
#define MAX_S2   512
#define MAX_U2   512
#define MAX_U1   8192
#define MAX_E1   16384
#define MAXDW    128        // per-node in-degree cap in P4 (Poisson(16))
#define NFLAG    131072
#define BMWORDS  4096

__device__ int   d_flag1[NFLAG], d_flag2[NFLAG];
__device__ int   d_idx1[NFLAG],  d_idx2[NFLAG];
__device__ int   d_s2src[MAX_S2];
__device__ int   d_uniq2[MAX_U2];
__device__ int   d_uniq1[MAX_U1];
__device__ int   d_e1src[MAX_E1], d_e1dst[MAX_E1];
__device__ int   d_cnt[4];                 // 0:n_s2 1:n_u2 2:n_e1 3:n_u1
__device__ float d_h0[MAX_U1 * 64];
__device__ float d_as1[MAX_U1 * 2], d_ad1[MAX_U1 * 2];
__device__ float d_ht2[MAX_U2 * 128];
__device__ float d_as2[MAX_U2 * 2], d_ad2[MAX_U2 * 2];
__device__ volatile int d_bar_gen;
__device__ int   d_bar_cnt;
__device__ volatile int d_fin;             // arrival count for final barrier

__device__ __forceinline__ float lrelu(float x, float s) {
    return x > 0.f ? x : s * x;
}

__device__ __forceinline__ void add_uniq2(int u) {
    if (atomicCAS(&d_flag2[u], 0, 1) == 0) {
        int p = atomicAdd(&d_cnt[1], 1);
        if (p < MAX_U2) { d_uniq2[p] = u; d_idx2[u] = p; }
    }
}
__device__ __forceinline__ void add_uniq1(int u) {
    if (atomicCAS(&d_flag1[u], 0, 1) == 0) {
        int p = atomicAdd(&d_cnt[3], 1);
        if (p < MAX_U1) { d_uniq1[p] = u; d_idx1[u] = p; }
    }
}

// R6 grid barrier (empirically best)
__device__ __forceinline__ void gsync() {
    __syncthreads();
    if (threadIdx.x == 0) {
        __threadfence();
        int g = d_bar_gen;
        if (atomicAdd(&d_bar_cnt, 1) == NB - 1) {
            d_bar_cnt = 0;
            __threadfence();
            d_bar_gen = g + 1;
        } else {
            while (d_bar_gen == g) { __nanosleep(32); }
        }
        __threadfence();
    }
    __syncthreads();
}

__device__ __forceinline__ void p1_hit(const int* ei, int e) {
    int s = ei[e];
    int p = atomicAdd(&d_cnt[0], 1);
    if (p < MAX_S2) d_s2src[p] = s;
    add_uniq2(s); add_uniq1(s);
}
__device__ __forceinline__ void p2_hit(const int* ei, int e, int d) {
    int s = ei[e];
    int p = atomicAdd(&d_cnt[2], 1);
    if (p < MAX_E1) { d_e1src[p] = s; d_e1dst[p] = d; }
    add_uniq1(s);
}

__device__ __forceinline__ float wredsum(float v) {
    #pragma unroll
    for (int o = 16; o > 0; o >>= 1) v += __shfl_xor_sync(0xffffffffu, v, o);
    return v;
}
__device__ __forceinline__ float wredmax(float v) {
    #pragma unroll
    for (int o = 16; o > 0; o >>= 1) v = fmaxf(v, __shfl_xor_sync(0xffffffffu, v, o));
    return v;
}

__global__ void __launch_bounds__(NT, 1)
gat_fused(const float* __restrict__ x,   const int* __restrict__ ei,
          const float* __restrict__ W1,  const float* __restrict__ asrc1,
          const float* __restrict__ adst1, const float* __restrict__ b1,
          const float* __restrict__ g1,  const float* __restrict__ be1,
          const float* __restrict__ mn1, const float* __restrict__ vr1,
          const float* __restrict__ W2,  const float* __restrict__ asrc2,
          const float* __restrict__ adst2, const float* __restrict__ b2,
          const float* __restrict__ g2,  const float* __restrict__ be2,
          const float* __restrict__ mn2, const float* __restrict__ vr2,
          const float* __restrict__ fcW, const float* __restrict__ fcb,
          float* __restrict__ out, int E, int target)
{
    // union pool: P2 bitmap (16KB) OR P4 per-warp lists (3 x 8KB = 24KB)
    __shared__ __align__(16) char s_pool[24 * 1024];
    unsigned* s_bm = (unsigned*)s_pool;                       // [BMWORDS]
    int*      wsiA = (int*)s_pool;                            // [16*MAXDW]
    float*    wa0A = (float*)(s_pool + 8 * 1024);             // [16*MAXDW]
    float*    wa1A = (float*)(s_pool + 16 * 1024);            // [16*MAXDW]

    __shared__ float xs[128], part[NT], hs[128];
    __shared__ int   s_si[MAX_S2 + 1];
    __shared__ float s_a0[MAX_S2 + 1], s_a1[MAX_S2 + 1];
    __shared__ float s_inv0, s_inv1;

    const int tid  = threadIdx.x;
    const int lane = tid & 31;
    const int wrp  = tid >> 5;
    const int bid  = blockIdx.x;
    const int gtid = bid * NT + tid;
    const int gstr = NB * NT;
    const int* dstp = ei + E;
    const int n4 = E >> 2;
    const int4* d4 = (const int4*)dstp;

    // ---------------- P1: edges into TARGET ---------------------------------
    if (gtid == 0) { add_uniq2(target); add_uniq1(target); }
    {
        for (int base = gtid; base < n4; base += gstr * SCAN_U) {
            int4 v[SCAN_U]; int idx[SCAN_U];
            #pragma unroll
            for (int u = 0; u < SCAN_U; u++) {
                idx[u] = base + u * gstr;
                v[u] = (idx[u] < n4) ? d4[idx[u]] : make_int4(-1, -1, -1, -1);
            }
            #pragma unroll
            for (int u = 0; u < SCAN_U; u++) {
                int i = idx[u];
                if (v[u].x == target) p1_hit(ei, 4*i+0);
                if (v[u].y == target) p1_hit(ei, 4*i+1);
                if (v[u].z == target) p1_hit(ei, 4*i+2);
                if (v[u].w == target) p1_hit(ei, 4*i+3);
            }
        }
        for (int e = (n4 << 2) + gtid; e < E; e += gstr)
            if (dstp[e] == target) p1_hit(ei, e);
    }
    gsync();

    // ---------------- P2: edges into uniq2 (shared bitmap) ------------------
    {
        for (int w = tid; w < BMWORDS; w += NT) s_bm[w] = 0u;
        __syncthreads();
        int n2 = min(d_cnt[1], MAX_U2);
        for (int t = tid; t < n2; t += NT) {
            int u = d_uniq2[t];
            atomicOr(&s_bm[u >> 5], 1u << (u & 31));
        }
        __syncthreads();
        for (int base = gtid; base < n4; base += gstr * SCAN_U) {
            int4 v[SCAN_U]; int idx[SCAN_U];
            #pragma unroll
            for (int u = 0; u < SCAN_U; u++) {
                idx[u] = base + u * gstr;
                v[u] = (idx[u] < n4) ? d4[idx[u]] : make_int4(-1, -1, -1, -1);
            }
            #pragma unroll
            for (int u = 0; u < SCAN_U; u++) {
                int i = idx[u];
                int dx = v[u].x, dy = v[u].y, dz = v[u].z, dw = v[u].w;
                if (dx >= 0 && ((s_bm[dx >> 5] >> (dx & 31)) & 1u)) p2_hit(ei, 4*i+0, dx);
                if (dy >= 0 && ((s_bm[dy >> 5] >> (dy & 31)) & 1u)) p2_hit(ei, 4*i+1, dy);
                if (dz >= 0 && ((s_bm[dz >> 5] >> (dz & 31)) & 1u)) p2_hit(ei, 4*i+2, dz);
                if (dw >= 0 && ((s_bm[dw >> 5] >> (dw & 31)) & 1u)) p2_hit(ei, 4*i+3, dw);
            }
        }
        for (int e = (n4 << 2) + gtid; e < E; e += gstr) {
            int d = dstp[e];
            if ((s_bm[d >> 5] >> (d & 31)) & 1u) p2_hit(ei, e, d);
        }
    }
    gsync();

    // snapshot counters (final from here on)
    const int ns2 = min(d_cnt[0], MAX_S2);
    const int nu2 = min(d_cnt[1], MAX_U2);
    const int ne1 = min(d_cnt[2], MAX_E1);
    const int nu1 = min(d_cnt[3], MAX_U1);

    // ---------------- P3: h0 = x@W1 (R6 block-per-node) ---------------------
    {
        int j  = tid & 63;
        int kq = tid >> 6;          // 0..7 -> 16 k's each
        for (int ui = bid; ui < nu1; ui += NB) {
            int u = d_uniq1[ui];
            if (tid < 128) xs[tid] = x[(size_t)u * 128 + tid];
            __syncthreads();
            float acc = 0.f;
            #pragma unroll
            for (int k = 0; k < 16; k++)
                acc = fmaf(xs[kq * 16 + k], W1[(kq * 16 + k) * 64 + j], acc);
            part[tid] = acc;
            __syncthreads();
            if (tid < 64) {
                float h = 0.f;
                #pragma unroll
                for (int q = 0; q < 8; q++) h += part[j + q * 64];
                d_h0[ui * 64 + j] = h;
                float vs = h * asrc1[j];
                float vd = h * adst1[j];
                #pragma unroll
                for (int o = 16; o > 0; o >>= 1) {
                    vs += __shfl_xor_sync(0xffffffffu, vs, o);
                    vd += __shfl_xor_sync(0xffffffffu, vd, o);
                }
                if ((j & 31) == 0) {
                    int hh = j >> 5;
                    d_as1[ui * 2 + hh] = vs;
                    d_ad1[ui * 2 + hh] = vd;
                }
            }
            __syncthreads();
        }
    }

    // ---------------- final barrier: blocks 1..147 cleanup + exit ------------
    if (bid != 0) {
        __syncthreads();
        int str = (NB - 1) * NT;
        int off = (bid - 1) * NT + tid;
        for (int i = off; i < nu1; i += str) d_flag1[d_uniq1[i]] = 0;
        for (int i = off; i < nu2; i += str) d_flag2[d_uniq2[i]] = 0;
        __syncthreads();
        if (tid == 0) {
            __threadfence();
            atomicAdd((int*)&d_fin, 1);
        }
        return;
    }
    // block 0 waits for all other blocks (their P3 + cleanup done)
    __syncthreads();
    if (tid == 0) {
        while (d_fin < NB - 1) { __nanosleep(32); }
        d_fin = 0;
        __threadfence();
    }
    __syncthreads();

    // ---------------- P4 (block 0): warp-per-node layer-1 GAT + W2 ----------
    {
        int*   wsi = &wsiA[wrp * MAXDW];
        float* wa0 = &wa0A[wrp * MAXDW];
        float* wa1 = &wa1A[wrp * MAXDW];
        for (int vi = wrp; vi < nu2; vi += 16) {
            int vnode = d_uniq2[vi];
            int vIdx  = d_idx1[vnode];
            float ad0 = d_ad1[vIdx * 2 + 0];
            float ad1 = d_ad1[vIdx * 2 + 1];
            // gather matched edges (self loop first) via ballot compaction
            if (lane == 0) wsi[0] = vIdx;
            int cnt = 1;
            for (int i = lane; i < ((ne1 + 31) & ~31); i += 32) {
                int d = (i < ne1) ? d_e1dst[i] : -1;
                bool hit = (d == vnode);
                unsigned m = __ballot_sync(0xffffffffu, hit);
                if (hit) {
                    int pos = cnt + __popc(m & ((1u << lane) - 1u));
                    if (pos < MAXDW) wsi[pos] = d_idx1[d_e1src[i]];
                }
                cnt += __popc(m);
            }
            cnt = min(cnt, MAXDW);
            __syncwarp();
            // softmax logits
            float lm0 = -1e30f, lm1 = -1e30f;
            for (int k = lane; k < cnt; k += 32) {
                int si = wsi[k];
                float e0 = lrelu(d_as1[si * 2 + 0] + ad0, 0.2f);
                float e1 = lrelu(d_as1[si * 2 + 1] + ad1, 0.2f);
                wa0[k] = e0; wa1[k] = e1;
                lm0 = fmaxf(lm0, e0); lm1 = fmaxf(lm1, e1);
            }
            float m0 = wredmax(lm0), m1 = wredmax(lm1);
            float ls0 = 0.f, ls1 = 0.f;
            for (int k = lane; k < cnt; k += 32) {
                float a0 = __expf(wa0[k] - m0);
                float a1 = __expf(wa1[k] - m1);
                wa0[k] = a0; wa1[k] = a1;
                ls0 += a0; ls1 += a1;
            }
            float inv0 = 1.f / (wredsum(ls0) + 1e-16f);
            float inv1 = 1.f / (wredsum(ls1) + 1e-16f);
            __syncwarp();
            // h1: lane holds dims j=lane (head0) and j=32+lane (head1)
            float acc0 = 0.f, acc1 = 0.f;
            #pragma unroll 4
            for (int k = 0; k < cnt; k++) {
                int si = wsi[k];
                acc0 = fmaf(wa0[k], d_h0[si * 64 + lane],      acc0);
                acc1 = fmaf(wa1[k], d_h0[si * 64 + 32 + lane], acc1);
            }
            acc0 *= inv0; acc1 *= inv1;
            int j0 = lane, j1 = 32 + lane;
            float o0 = lrelu(acc0 + b1[j0], 0.01f);
            o0 = (o0 - mn1[j0]) * rsqrtf(vr1[j0] + 1e-5f) * g1[j0] + be1[j0];
            float o1 = lrelu(acc1 + b1[j1], 0.01f);
            o1 = (o1 - mn1[j1]) * rsqrtf(vr1[j1] + 1e-5f) * g1[j1] + be1[j1];
            // ht2 = h1 @ W2 : lane covers j = lane*4 .. lane*4+3
            float4 r = make_float4(0.f, 0.f, 0.f, 0.f);
            #pragma unroll
            for (int k = 0; k < 64; k++) {
                float hk = (k < 32) ? __shfl_sync(0xffffffffu, o0, k)
                                    : __shfl_sync(0xffffffffu, o1, k - 32);
                float4 w = *(const float4*)&W2[k * 128 + lane * 4];
                r.x = fmaf(hk, w.x, r.x);
                r.y = fmaf(hk, w.y, r.y);
                r.z = fmaf(hk, w.z, r.z);
                r.w = fmaf(hk, w.w, r.w);
            }
            *(float4*)&d_ht2[vi * 128 + lane * 4] = r;
            // as2/ad2: lanes 0..15 -> head0 (j<64), lanes 16..31 -> head1
            int jb = lane * 4;
            float ps = r.x * asrc2[jb] + r.y * asrc2[jb + 1]
                     + r.z * asrc2[jb + 2] + r.w * asrc2[jb + 3];
            float pd = r.x * adst2[jb] + r.y * adst2[jb + 1]
                     + r.z * adst2[jb + 2] + r.w * adst2[jb + 3];
            #pragma unroll
            for (int o = 8; o > 0; o >>= 1) {
                ps += __shfl_xor_sync(0xffffffffu, ps, o);
                pd += __shfl_xor_sync(0xffffffffu, pd, o);
            }
            if (lane == 0)  { d_as2[vi * 2 + 0] = ps; d_ad2[vi * 2 + 0] = pd; }
            if (lane == 16) { d_as2[vi * 2 + 1] = ps; d_ad2[vi * 2 + 1] = pd; }
            __syncwarp();
        }
    }
    __syncthreads();

    // ---------------- P5 (block 0): layer-2 at TARGET + BN + FC -------------
    {
        int cnt = ns2 + 1;                       // + self loop
        if (tid < 32) {                          // warp-0 softmax
            int u_t = d_idx2[target];
            float ad0 = d_ad2[u_t * 2 + 0];
            float ad1 = d_ad2[u_t * 2 + 1];
            float lm0 = -1e30f, lm1 = -1e30f;
            for (int k = lane; k < cnt; k += 32) {
                int src = (k == ns2) ? target : d_s2src[k];
                int si = d_idx2[src];
                s_si[k] = si;
                float e0 = lrelu(d_as2[si * 2 + 0] + ad0, 0.2f);
                float e1 = lrelu(d_as2[si * 2 + 1] + ad1, 0.2f);
                s_a0[k] = e0; s_a1[k] = e1;
                lm0 = fmaxf(lm0, e0); lm1 = fmaxf(lm1, e1);
            }
            float m0 = wredmax(lm0), m1 = wredmax(lm1);
            float ls0 = 0.f, ls1 = 0.f;
            for (int k = lane; k < cnt; k += 32) {
                float a0 = __expf(s_a0[k] - m0);
                float a1 = __expf(s_a1[k] - m1);
                s_a0[k] = a0; s_a1[k] = a1;
                ls0 += a0; ls1 += a1;
            }
            float sum0 = wredsum(ls0), sum1 = wredsum(ls1);
            if (lane == 0) {
                s_inv0 = 1.f / (sum0 + 1e-16f);
                s_inv1 = 1.f / (sum1 + 1e-16f);
            }
        }
        __syncthreads();
        if (tid < 128) {
            int j = tid;
            const float* sa = (j >= 64) ? s_a1 : s_a0;
            float inv = (j >= 64) ? s_inv1 : s_inv0;
            float acc = 0.f;
            for (int k = 0; k < cnt; k++)
                acc = fmaf(sa[k], d_ht2[s_si[k] * 128 + j], acc);
            acc *= inv;
            float o = acc + b2[j];
            o = lrelu(o, 0.01f);
            o = (o - mn2[j]) * rsqrtf(vr2[j] + 1e-5f) * g2[j] + be2[j];
            hs[j] = o;
        }
        __syncthreads();
        if (tid < 60) {
            float r = fcb[tid];
            #pragma unroll 4
            for (int q = 0; q < 128; q++) r = fmaf(hs[q], fcW[q * 60 + tid], r);
            out[tid] = r;
        }
        __syncthreads();
        if (tid < 4) d_cnt[tid] = 0;             // state reset for next replay
    }
}

// ---------------------------------------------------------------------------
extern "C" void kernel_launch(void* const* d_in, const int* in_sizes, int n_in,
                              void* d_out, int out_size) {
    const float* x      = (const float*)d_in[0];
    const int*   ei     = (const int*)d_in[1];     // int32 (JAX x64 disabled)
    const float* W1     = (const float*)d_in[2];
    const float* asrc1  = (const float*)d_in[3];
    const float* adst1  = (const float*)d_in[4];
    const float* b1     = (const float*)d_in[5];
    const float* g1     = (const float*)d_in[6];
    const float* be1    = (const float*)d_in[7];
    const float* mn1    = (const float*)d_in[8];
    const float* vr1    = (const float*)d_in[9];
    const float* W2     = (const float*)d_in[10];
    const float* asrc2  = (const float*)d_in[11];
    const float* adst2  = (const float*)d_in[12];
    const float* b2     = (const float*)d_in[13];
    const float* g2     = (const float*)d_in[14];
    const float* be2    = (const float*)d_in[15];
    const float* mn2    = (const float*)d_in[16];
    const float* vr2    = (const float*)d_in[17];
    const float* fcW    = (const float*)d_in[18];
    const float* fcb    = (const float*)d_in[19];
    float*       out    = (float*)d_out;

    int N = in_sizes[0] / 128;
    int E = in_sizes[1] / 2;
    int target = N - 1;

    gat_fused<<<NB, NT>>>(x, ei, W1, asrc1, adst1, b1, g1, be1, mn1, vr1,
                          W2, asrc2, adst2, b2, g2, be2, mn2, vr2, fcW, fcb,
                          out, E, target);
}

// round 10
// speedup vs baseline: 1.2745x; 1.2745x over previous
#include <cuda_runtime.h>

// ---------------------------------------------------------------------------
// GAT returning only h[N-1]: cone pruning, single persistent kernel.
// R10 = exact R6 base (best: 40.6us) + ONE change: P4/P5 softmax reductions
// done by warp 0 via shfl (replaces 4+4 block-wide tree reductions, each
// ~9 __syncthreads rounds), and __expf instead of expf. Nothing else moved.
// ---------------------------------------------------------------------------

#define NB       148        // 1 block per SM -> guaranteed co-resident
#define NT       512
#define SCAN_U   4
#define MAX_S2   512
#define MAX_U2   512
#define MAX_U1   8192
#define MAX_E1   16384
#define MAXD     512
#define NFLAG    131072
#define BMWORDS  4096

__device__ int   d_flag1[NFLAG], d_flag2[NFLAG];
__device__ int   d_idx1[NFLAG],  d_idx2[NFLAG];
__device__ int   d_s2src[MAX_S2];
__device__ int   d_uniq2[MAX_U2];
__device__ int   d_uniq1[MAX_U1];
__device__ int   d_e1src[MAX_E1], d_e1dst[MAX_E1];
__device__ int   d_cnt[4];                 // 0:n_s2 1:n_u2 2:n_e1 3:n_u1
__device__ float d_h0[MAX_U1 * 64];
__device__ float d_as1[MAX_U1 * 2], d_ad1[MAX_U1 * 2];
__device__ float d_ht2[MAX_U2 * 128];
__device__ float d_as2[MAX_U2 * 2], d_ad2[MAX_U2 * 2];
__device__ volatile int d_bar_gen;
__device__ int   d_bar_cnt;

__device__ __forceinline__ float lrelu(float x, float s) {
    return x > 0.f ? x : s * x;
}

__device__ __forceinline__ void add_uniq2(int u) {
    if (atomicCAS(&d_flag2[u], 0, 1) == 0) {
        int p = atomicAdd(&d_cnt[1], 1);
        if (p < MAX_U2) { d_uniq2[p] = u; d_idx2[u] = p; }
    }
}
__device__ __forceinline__ void add_uniq1(int u) {
    if (atomicCAS(&d_flag1[u], 0, 1) == 0) {
        int p = atomicAdd(&d_cnt[3], 1);
        if (p < MAX_U1) { d_uniq1[p] = u; d_idx1[u] = p; }
    }
}

// grid-wide barrier: all NB blocks must call (R6 version, empirically best)
__device__ __forceinline__ void gsync() {
    __syncthreads();
    if (threadIdx.x == 0) {
        __threadfence();
        int g = d_bar_gen;
        if (atomicAdd(&d_bar_cnt, 1) == NB - 1) {
            d_bar_cnt = 0;
            __threadfence();
            d_bar_gen = g + 1;
        } else {
            while (d_bar_gen == g) { __nanosleep(32); }
        }
        __threadfence();
    }
    __syncthreads();
}

__device__ __forceinline__ void p1_hit(const int* ei, int e) {
    int s = ei[e];
    int p = atomicAdd(&d_cnt[0], 1);
    if (p < MAX_S2) d_s2src[p] = s;
    add_uniq2(s); add_uniq1(s);
}
__device__ __forceinline__ void p2_hit(const int* ei, int e, int d) {
    int s = ei[e];
    int p = atomicAdd(&d_cnt[2], 1);
    if (p < MAX_E1) { d_e1src[p] = s; d_e1dst[p] = d; }
    add_uniq1(s);
}

__device__ __forceinline__ float wredsum(float v) {
    #pragma unroll
    for (int o = 16; o > 0; o >>= 1) v += __shfl_xor_sync(0xffffffffu, v, o);
    return v;
}
__device__ __forceinline__ float wredmax(float v) {
    #pragma unroll
    for (int o = 16; o > 0; o >>= 1) v = fmaxf(v, __shfl_xor_sync(0xffffffffu, v, o));
    return v;
}

__global__ void __launch_bounds__(NT, 1)
gat_fused(const float* __restrict__ x,   const int* __restrict__ ei,
          const float* __restrict__ W1,  const float* __restrict__ asrc1,
          const float* __restrict__ adst1, const float* __restrict__ b1,
          const float* __restrict__ g1,  const float* __restrict__ be1,
          const float* __restrict__ mn1, const float* __restrict__ vr1,
          const float* __restrict__ W2,  const float* __restrict__ asrc2,
          const float* __restrict__ adst2, const float* __restrict__ b2,
          const float* __restrict__ g2,  const float* __restrict__ be2,
          const float* __restrict__ mn2, const float* __restrict__ vr2,
          const float* __restrict__ fcW, const float* __restrict__ fcb,
          float* __restrict__ out, int E, int target)
{
    __shared__ unsigned s_bm[BMWORDS];               // 16 KB (P2)
    __shared__ int   s_si[MAXD + 8];
    __shared__ float s_a0[MAXD + 8], s_a1[MAXD + 8];
    __shared__ float xs[128], part[NT], hs[128];
    __shared__ float ss[4], sd[4];
    __shared__ float s_inv0, s_inv1;
    __shared__ int   s_scnt;

    const int tid  = threadIdx.x;
    const int lane = tid & 31;
    const int gtid = blockIdx.x * NT + tid;
    const int gstr = NB * NT;
    const int* dstp = ei + E;
    const int n4 = E >> 2;
    const int4* d4 = (const int4*)dstp;

    // ---------------- P1: edges into TARGET ---------------------------------
    if (gtid == 0) { add_uniq2(target); add_uniq1(target); }
    {
        for (int base = gtid; base < n4; base += gstr * SCAN_U) {
            int4 v[SCAN_U]; int idx[SCAN_U];
            #pragma unroll
            for (int u = 0; u < SCAN_U; u++) {
                idx[u] = base + u * gstr;
                v[u] = (idx[u] < n4) ? d4[idx[u]] : make_int4(-1, -1, -1, -1);
            }
            #pragma unroll
            for (int u = 0; u < SCAN_U; u++) {
                int i = idx[u];
                if (v[u].x == target) p1_hit(ei, 4*i+0);
                if (v[u].y == target) p1_hit(ei, 4*i+1);
                if (v[u].z == target) p1_hit(ei, 4*i+2);
                if (v[u].w == target) p1_hit(ei, 4*i+3);
            }
        }
        for (int e = (n4 << 2) + gtid; e < E; e += gstr)
            if (dstp[e] == target) p1_hit(ei, e);
    }
    gsync();

    // ---------------- P2: edges into uniq2 (shared bitmap) ------------------
    {
        for (int w = tid; w < BMWORDS; w += NT) s_bm[w] = 0u;
        __syncthreads();
        int n2 = min(d_cnt[1], MAX_U2);
        for (int t = tid; t < n2; t += NT) {
            int u = d_uniq2[t];
            atomicOr(&s_bm[u >> 5], 1u << (u & 31));
        }
        __syncthreads();
        for (int base = gtid; base < n4; base += gstr * SCAN_U) {
            int4 v[SCAN_U]; int idx[SCAN_U];
            #pragma unroll
            for (int u = 0; u < SCAN_U; u++) {
                idx[u] = base + u * gstr;
                v[u] = (idx[u] < n4) ? d4[idx[u]] : make_int4(-1, -1, -1, -1);
            }
            #pragma unroll
            for (int u = 0; u < SCAN_U; u++) {
                int i = idx[u];
                int dx = v[u].x, dy = v[u].y, dz = v[u].z, dw = v[u].w;
                if (dx >= 0 && ((s_bm[dx >> 5] >> (dx & 31)) & 1u)) p2_hit(ei, 4*i+0, dx);
                if (dy >= 0 && ((s_bm[dy >> 5] >> (dy & 31)) & 1u)) p2_hit(ei, 4*i+1, dy);
                if (dz >= 0 && ((s_bm[dz >> 5] >> (dz & 31)) & 1u)) p2_hit(ei, 4*i+2, dz);
                if (dw >= 0 && ((s_bm[dw >> 5] >> (dw & 31)) & 1u)) p2_hit(ei, 4*i+3, dw);
            }
        }
        for (int e = (n4 << 2) + gtid; e < E; e += gstr) {
            int d = dstp[e];
            if ((s_bm[d >> 5] >> (d & 31)) & 1u) p2_hit(ei, e, d);
        }
    }
    gsync();

    // snapshot counters (stable from here on)
    const int ns2 = min(d_cnt[0], MAX_S2);
    const int nu2 = min(d_cnt[1], MAX_U2);
    const int ne1 = min(d_cnt[2], MAX_E1);
    const int nu1 = min(d_cnt[3], MAX_U1);

    // ---------------- P3: h0 = x@W1 for uniq1 nodes (R6 layout) -------------
    {
        int j  = tid & 63;
        int kq = tid >> 6;          // 0..7 -> 16 k's each
        for (int ui = blockIdx.x; ui < nu1; ui += NB) {
            int u = d_uniq1[ui];
            if (tid < 128) xs[tid] = x[(size_t)u * 128 + tid];
            __syncthreads();
            float acc = 0.f;
            #pragma unroll
            for (int k = 0; k < 16; k++)
                acc = fmaf(xs[kq * 16 + k], W1[(kq * 16 + k) * 64 + j], acc);
            part[tid] = acc;
            __syncthreads();
            if (tid < 64) {
                float h = 0.f;
                #pragma unroll
                for (int q = 0; q < 8; q++) h += part[j + q * 64];
                d_h0[ui * 64 + j] = h;
                float vs = h * asrc1[j];
                float vd = h * adst1[j];
                #pragma unroll
                for (int o = 16; o > 0; o >>= 1) {
                    vs += __shfl_xor_sync(0xffffffffu, vs, o);
                    vd += __shfl_xor_sync(0xffffffffu, vd, o);
                }
                if ((j & 31) == 0) {
                    int hh = j >> 5;
                    d_as1[ui * 2 + hh] = vs;
                    d_ad1[ui * 2 + hh] = vd;
                }
            }
            __syncthreads();
        }
    }
    gsync();

    // ---------------- P4: layer-1 GAT + projection per uniq2 node -----------
    {
        for (int vi = blockIdx.x; vi < nu2; vi += NB) {
            int vnode = d_uniq2[vi];
            int vIdx  = d_idx1[vnode];
            if (tid == 0) { s_scnt = 1; s_si[0] = vIdx; }   // self loop
            __syncthreads();
            for (int i = tid; i < ne1; i += NT) {
                if (d_e1dst[i] == vnode) {
                    int p = atomicAdd(&s_scnt, 1);
                    if (p < MAXD) s_si[p] = d_idx1[d_e1src[i]];
                }
            }
            __syncthreads();
            int cnt = min(s_scnt, MAXD);
            // ---- CHANGED vs R6: warp-0 shfl softmax (was 4 tree reductions)
            if (tid < 32) {
                float ad0 = d_ad1[vIdx * 2 + 0];
                float ad1 = d_ad1[vIdx * 2 + 1];
                float lm0 = -1e30f, lm1 = -1e30f;
                for (int k = lane; k < cnt; k += 32) {
                    int si = s_si[k];
                    float e0 = lrelu(d_as1[si * 2 + 0] + ad0, 0.2f);
                    float e1 = lrelu(d_as1[si * 2 + 1] + ad1, 0.2f);
                    s_a0[k] = e0; s_a1[k] = e1;
                    lm0 = fmaxf(lm0, e0); lm1 = fmaxf(lm1, e1);
                }
                float m0 = wredmax(lm0), m1 = wredmax(lm1);
                float ls0 = 0.f, ls1 = 0.f;
                for (int k = lane; k < cnt; k += 32) {
                    float a0 = __expf(s_a0[k] - m0);
                    float a1 = __expf(s_a1[k] - m1);
                    s_a0[k] = a0; s_a1[k] = a1;
                    ls0 += a0; ls1 += a1;
                }
                float sum0 = wredsum(ls0), sum1 = wredsum(ls1);
                if (lane == 0) {
                    s_inv0 = 1.f / (sum0 + 1e-16f);
                    s_inv1 = 1.f / (sum1 + 1e-16f);
                }
            }
            __syncthreads();
            if (tid < 64) {
                int j = tid;
                const float* sa = (j >= 32) ? s_a1 : s_a0;
                float inv = (j >= 32) ? s_inv1 : s_inv0;
                float acc = 0.f;
                for (int k = 0; k < cnt; k++)
                    acc = fmaf(sa[k], d_h0[s_si[k] * 64 + j], acc);
                acc *= inv;
                float o = acc + b1[j];
                o = lrelu(o, 0.01f);
                o = (o - mn1[j]) * rsqrtf(vr1[j] + 1e-5f) * g1[j] + be1[j];
                hs[j] = o;
            }
            __syncthreads();
            if (tid < 128) {
                int j = tid;
                float acc = 0.f;
                #pragma unroll
                for (int k = 0; k < 64; k++) acc = fmaf(hs[k], W2[k * 128 + j], acc);
                d_ht2[vi * 128 + j] = acc;
                float vs = wredsum(acc * asrc2[j]);
                float vd = wredsum(acc * adst2[j]);
                int w = j >> 5;
                if ((j & 31) == 0) { ss[w] = vs; sd[w] = vd; }
            }
            __syncthreads();
            if (tid == 0) {
                d_as2[vi * 2 + 0] = ss[0] + ss[1];
                d_as2[vi * 2 + 1] = ss[2] + ss[3];
                d_ad2[vi * 2 + 0] = sd[0] + sd[1];
                d_ad2[vi * 2 + 1] = sd[2] + sd[3];
            }
            __syncthreads();
        }
    }
    gsync();

    // ---------------- P5 (block 0) | cleanup happens below out write --------
    if (blockIdx.x != 0) return;
    {
        int cnt = ns2 + 1;                       // + self loop
        // ---- CHANGED vs R6: warp-0 shfl softmax (was 4 tree reductions)
        if (tid < 32) {
            int u_t = d_idx2[target];
            float ad0 = d_ad2[u_t * 2 + 0];
            float ad1 = d_ad2[u_t * 2 + 1];
            float lm0 = -1e30f, lm1 = -1e30f;
            for (int k = lane; k < cnt; k += 32) {
                int src = (k == ns2) ? target : d_s2src[k];
                int si = d_idx2[src];
                s_si[k] = si;
                float e0 = lrelu(d_as2[si * 2 + 0] + ad0, 0.2f);
                float e1 = lrelu(d_as2[si * 2 + 1] + ad1, 0.2f);
                s_a0[k] = e0; s_a1[k] = e1;
                lm0 = fmaxf(lm0, e0); lm1 = fmaxf(lm1, e1);
            }
            float m0 = wredmax(lm0), m1 = wredmax(lm1);
            float ls0 = 0.f, ls1 = 0.f;
            for (int k = lane; k < cnt; k += 32) {
                float a0 = __expf(s_a0[k] - m0);
                float a1 = __expf(s_a1[k] - m1);
                s_a0[k] = a0; s_a1[k] = a1;
                ls0 += a0; ls1 += a1;
            }
            float sum0 = wredsum(ls0), sum1 = wredsum(ls1);
            if (lane == 0) {
                s_inv0 = 1.f / (sum0 + 1e-16f);
                s_inv1 = 1.f / (sum1 + 1e-16f);
            }
        }
        __syncthreads();
        if (tid < 128) {
            int j = tid;
            const float* sa = (j >= 64) ? s_a1 : s_a0;
            float inv = (j >= 64) ? s_inv1 : s_inv0;
            float acc = 0.f;
            for (int k = 0; k < cnt; k++)
                acc = fmaf(sa[k], d_ht2[s_si[k] * 128 + j], acc);
            acc *= inv;
            float o = acc + b2[j];
            o = lrelu(o, 0.01f);
            o = (o - mn2[j]) * rsqrtf(vr2[j] + 1e-5f) * g2[j] + be2[j];
            hs[j] = o;
        }
        __syncthreads();
        if (tid < 60) {
            float r = fcb[tid];
            #pragma unroll 4
            for (int q = 0; q < 128; q++) r = fmaf(hs[q], fcW[q * 60 + tid], r);
            out[tid] = r;
        }
        // cleanup for next graph replay (after out[] written, as in R6)
        __syncthreads();
        for (int i = tid; i < nu1; i += NT) d_flag1[d_uniq1[i]] = 0;
        for (int i = tid; i < nu2; i += NT) d_flag2[d_uniq2[i]] = 0;
        __syncthreads();
        if (tid < 4) d_cnt[tid] = 0;
    }
}

// ---------------------------------------------------------------------------
extern "C" void kernel_launch(void* const* d_in, const int* in_sizes, int n_in,
                              void* d_out, int out_size) {
    const float* x      = (const float*)d_in[0];
    const int*   ei     = (const int*)d_in[1];     // int32 (JAX x64 disabled)
    const float* W1     = (const float*)d_in[2];
    const float* asrc1  = (const float*)d_in[3];
    const float* adst1  = (const float*)d_in[4];
    const float* b1     = (const float*)d_in[5];
    const float* g1     = (const float*)d_in[6];
    const float* be1    = (const float*)d_in[7];
    const float* mn1    = (const float*)d_in[8];
    const float* vr1    = (const float*)d_in[9];
    const float* W2     = (const float*)d_in[10];
    const float* asrc2  = (const float*)d_in[11];
    const float* adst2  = (const float*)d_in[12];
    const float* b2     = (const float*)d_in[13];
    const float* g2     = (const float*)d_in[14];
    const float* be2    = (const float*)d_in[15];
    const float* mn2    = (const float*)d_in[16];
    const float* vr2    = (const float*)d_in[17];
    const float* fcW    = (const float*)d_in[18];
    const float* fcb    = (const float*)d_in[19];
    float*       out    = (float*)d_out;

    int N = in_sizes[0] / 128;
    int E = in_sizes[1] / 2;
    int target = N - 1;

    gat_fused<<<NB, NT>>>(x, ei, W1, asrc1, adst1, b1, g1, be1, mn1, vr1,
                          W2, asrc2, adst2, b2, g2, be2, mn2, vr2, fcW, fcb,
                          out, E, target);
}